// round 16
// baseline (speedup 1.0000x reference)
#include <cuda_runtime.h>
#include <cuda_fp16.h>
#include <math.h>
#include <stdint.h>

#define BATCH 64
#define NF    1024
#define DIM   256
#define NEG   0.2f

// ================= device scratch (no allocs allowed) ========================
// gamma != 0 fallback path (fp32)
__device__ __align__(16) float g_q [BATCH*NF*DIM];
__device__ __align__(16) float g_k [BATCH*NF*DIM];
__device__ __align__(16) float g_v [BATCH*NF*DIM];
__device__ __align__(16) float g_ao[BATCH*NF*DIM];
__device__ __align__(16) float g_xc[BATCH*2*NF*DIM];
__device__ __align__(16) float g_D [BATCH*DIM*DIM];
__device__ __align__(16) float g_Y [BATCH*NF*DIM];
// gamma == 0 tensor path (fp16, single-term everywhere)
__device__ __align__(16) __half g_ws_hi[DIM*NF];
__device__ __align__(16) __half g_x_hi [BATCH*NF*DIM];
__device__ __align__(16) __half g_xT_hi[BATCH*DIM*NF];
__device__ __align__(16) __half g_dw_hi[NF*NF];
__device__ __align__(16) __half g_DT_hi[BATCH*DIM*DIM];
__device__ __align__(16) __half g_YT_hi[BATCH*DIM*NF];

// ================= PTX helpers (family-safe: sm_80-era only) =================
__device__ __forceinline__ uint32_t s2u(const void* p) {
    uint32_t a;
    asm("{ .reg .u64 t; cvta.to.shared.u64 t, %1; cvt.u32.u64 %0, t; }" : "=r"(a) : "l"(p));
    return a;
}
__device__ __forceinline__ void cp16(uint32_t dst, const void* src) {
    asm volatile("cp.async.cg.shared.global [%0], [%1], 16;" :: "r"(dst), "l"(src));
}
#define CP_COMMIT() asm volatile("cp.async.commit_group;" ::: "memory")
#define CP_WAIT1()  asm volatile("cp.async.wait_group 1;"  ::: "memory")
#define CP_WAIT0()  asm volatile("cp.async.wait_group 0;"  ::: "memory")

__device__ __forceinline__ void ldm_x4(uint32_t& r0, uint32_t& r1, uint32_t& r2, uint32_t& r3,
                                       uint32_t addr) {
    asm volatile("ldmatrix.sync.aligned.m8n8.x4.shared.b16 {%0,%1,%2,%3}, [%4];"
                 : "=r"(r0), "=r"(r1), "=r"(r2), "=r"(r3) : "r"(addr));
}
__device__ __forceinline__ void mma_f16(float* c, const uint32_t* a, const uint32_t* b) {
    asm volatile("mma.sync.aligned.m16n8k16.row.col.f32.f16.f16.f32 "
                 "{%0,%1,%2,%3}, {%4,%5,%6,%7}, {%8,%9}, {%0,%1,%2,%3};"
                 : "+f"(c[0]), "+f"(c[1]), "+f"(c[2]), "+f"(c[3])
                 : "r"(a[0]), "r"(a[1]), "r"(a[2]), "r"(a[3]), "r"(b[0]), "r"(b[1]));
}
__device__ __forceinline__ uint32_t pack_h(__half a, __half b) {
    return (uint32_t)__half_as_ushort(a) | ((uint32_t)__half_as_ushort(b) << 16);
}

// ================= fp16 single-term HMMA GEMM ================================
// C[M,N] = epi( A@B^T ), all K-major operands, fp32 accumulate.
// CTA 128x128, 256 threads, warp grid 4x2, warp tile 32x64, K-chunk 64
// (halves sync/wait boundaries vs BK=32; 64 MMAs/warp/chunk amortize the
// ldmatrix dependency chain). 3-stage cp.async pipeline, ONE __syncthreads
// per chunk, loads for kk+2 issued BEFORE compute of kk.
// smem pitch 72 halfs (144B row stride): 8-row ldmatrix addresses hit the 8
// distinct 16B sectors mod 128 -> conflict-free.
// EPI 1: sigmoid(acc + bias[col]) -> fp16 row-major out
// EPI 2: leaky(acc)               -> fp16 row-major out
// EPI 3: leaky(acc + bias[row])   -> fp32 row-major out
#define BK     64
#define PITCH  72
#define TILE_B (128*PITCH*2)   // 18432
#define STAGE_F (2*TILE_B)     // 36864: A | B
#define NSTAGE 3               // 110592 bytes dyn smem; 2 CTAs = 216KB <= 228KB

template<int EPI>
__device__ void tgemm_body(const __half* __restrict__ Ahi,
                           const __half* __restrict__ Bhi,
                           int K, const float* __restrict__ bias,
                           __half* __restrict__ outH,
                           float* __restrict__ outF, int ldOut) {
    extern __shared__ char smc[];
    uint32_t sbase = s2u(smc);
    int tid = threadIdx.x, lane = tid & 31, wid = tid >> 5;   // 8 warps
    int mBase = blockIdx.y * 128, nBase = blockIdx.x * 128;
    int wRow = (wid >> 1) * 32, wCol = (wid & 1) * 64;

    int total = K / BK;
    int lrow = tid >> 1, lpart = tid & 1;   // 2 threads/row, 64B each

    auto load_stage = [&](int s, int kk) {
        int k0 = kk * BK;
        uint32_t st = sbase + (uint32_t)s * STAGE_F;
        #pragma unroll
        for (int t = 0; t < 2; t++) {
            const __half* S = t ? Bhi : Ahi;
            int rb = t ? nBase : mBase;
            const __half* rowp = S + (size_t)(rb + lrow) * K + k0 + lpart * 32;
            uint32_t dbase = st + (uint32_t)t * TILE_B + (uint32_t)(lrow * PITCH + lpart * 32) * 2;
            cp16(dbase,      rowp);
            cp16(dbase + 16, rowp + 8);
            cp16(dbase + 32, rowp + 16);
            cp16(dbase + 48, rowp + 24);
        }
        CP_COMMIT();
    };

    load_stage(0, 0);
    load_stage(1, 1);

    float acc[2][8][4];
    #pragma unroll
    for (int i = 0; i < 2; i++)
        #pragma unroll
        for (int j = 0; j < 8; j++)
            #pragma unroll
            for (int q = 0; q < 4; q++) acc[i][j][q] = 0.0f;

    int rs = 0, ws = 2;
    for (int kk = 0; kk < total; kk++) {
        if (kk + 1 < total) { CP_WAIT1(); } else { CP_WAIT0(); }
        __syncthreads();
        if (kk + 2 < total) load_stage(ws, kk + 2);

        uint32_t st = sbase + (uint32_t)rs * STAGE_F;
        uint32_t aT = st, bT = st + TILE_B;
        #pragma unroll
        for (int kf = 0; kf < 4; kf++) {
            uint32_t ah[2][4], bh[8][2];
            #pragma unroll
            for (int i = 0; i < 2; i++) {
                int r = wRow + i * 16 + (lane & 15);
                int c = kf * 16 + ((lane & 16) ? 8 : 0);
                ldm_x4(ah[i][0], ah[i][1], ah[i][2], ah[i][3],
                       aT + (uint32_t)(r * PITCH + c) * 2);
            }
            #pragma unroll
            for (int nf2 = 0; nf2 < 4; nf2++) {
                int n = wCol + nf2 * 16 + (lane & 7) + ((lane & 16) ? 8 : 0);
                int c = kf * 16 + ((lane & 8) ? 8 : 0);
                uint32_t r0, r1, r2, r3;
                ldm_x4(r0, r1, r2, r3, bT + (uint32_t)(n * PITCH + c) * 2);
                bh[nf2*2][0] = r0; bh[nf2*2][1] = r1;
                bh[nf2*2+1][0] = r2; bh[nf2*2+1][1] = r3;
            }
            #pragma unroll
            for (int i = 0; i < 2; i++)
                #pragma unroll
                for (int j = 0; j < 8; j++)
                    mma_f16(acc[i][j], ah[i], bh[j]);
        }
        rs = (rs == NSTAGE-1) ? 0 : rs + 1;
        ws = (ws == NSTAGE-1) ? 0 : ws + 1;
    }

    // ---- epilogue ----
    int r0 = mBase + wRow + (lane >> 2);
    int c0 = nBase + wCol + (lane & 3) * 2;
    #pragma unroll
    for (int i = 0; i < 2; i++) {
        #pragma unroll
        for (int h = 0; h < 2; h++) {
            int row = r0 + i * 16 + h * 8;
            float rbv = (EPI == 3) ? bias[row] : 0.0f;
            #pragma unroll
            for (int j = 0; j < 8; j++) {
                float v0 = acc[i][j][h*2+0];
                float v1 = acc[i][j][h*2+1];
                int col = c0 + j * 8;
                if (EPI == 1) {
                    v0 += bias[col]; v1 += bias[col + 1];
                    v0 = 1.0f / (1.0f + expf(-v0));
                    v1 = 1.0f / (1.0f + expf(-v1));
                } else if (EPI == 2) {
                    v0 = (v0 >= 0.f) ? v0 : NEG * v0;
                    v1 = (v1 >= 0.f) ? v1 : NEG * v1;
                } else {
                    v0 += rbv; v1 += rbv;
                    v0 = (v0 >= 0.f) ? v0 : NEG * v0;
                    v1 = (v1 >= 0.f) ? v1 : NEG * v1;
                }
                size_t off = (size_t)row * ldOut + col;
                if (EPI == 3) {
                    *reinterpret_cast<float2*>(outF + off) = make_float2(v0, v1);
                } else {
                    *reinterpret_cast<uint32_t*>(outH + off) =
                        pack_h(__float2half_rn(v0), __float2half_rn(v1));
                }
            }
        }
    }
}

// DT[l,o] = sigmoid( xT_b[l,:] . Wsum[o,:] + fc_b[o] )   M=256,N=256,K=1024
__global__ __launch_bounds__(256, 2)
void tgA(const float* __restrict__ gamma, const float* __restrict__ fc_b) {
    if (gamma[0] != 0.0f) return;
    size_t b = blockIdx.z;
    tgemm_body<1>(g_xT_hi + b * DIM * NF, g_ws_hi, NF, fc_b,
                  g_DT_hi + b * DIM * DIM, nullptr, DIM);
}
// YT[l,n] = leaky( DT_b[l,:] . x_b[n,:] )                 M=256,N=1024,K=256
__global__ __launch_bounds__(256, 2)
void tgB(const float* __restrict__ gamma) {
    if (gamma[0] != 0.0f) return;
    size_t b = blockIdx.z;
    tgemm_body<2>(g_DT_hi + b * DIM * DIM, g_x_hi + b * NF * DIM, DIM, nullptr,
                  g_YT_hi + b * DIM * NF, nullptr, NF);
}
// out[o,l] = leaky( dw[o,:] . YT_b[l,:] + dw_b[o] )       M=1024,N=256,K=1024
__global__ __launch_bounds__(256, 2)
void tgC(const float* __restrict__ gamma, const float* __restrict__ dw_b,
         float* __restrict__ out) {
    if (gamma[0] != 0.0f) return;
    size_t b = blockIdx.z;
    tgemm_body<3>(g_dw_hi, g_YT_hi + b * DIM * NF, NF, dw_b,
                  nullptr, out + b * NF * DIM, DIM);
}

// ================= conversion kernels (gamma == 0) ===========================
// weights: blocks [0,1024) -> wsum fold+convert; [1024,2048) -> dw convert
__global__ void conv_weights(const float* __restrict__ fc_w,
                             const float* __restrict__ dw_w,
                             const float* __restrict__ gamma) {
    if (gamma[0] != 0.0f) return;
    int blk = blockIdx.x;
    if (blk < 1024) {
        int i = blk * 256 + threadIdx.x;              // < DIM*NF
        int o = i >> 10, c = i & 1023;
        float w = fc_w[(size_t)o * 2048 + c] + fc_w[(size_t)o * 2048 + 1024 + c];
        g_ws_hi[i] = __float2half_rn(w);
    } else {
        size_t i = ((size_t)(blk - 1024) * 256 + threadIdx.x) * 4;   // < NF*NF
        float4 v = *reinterpret_cast<const float4*>(dw_w + i);
        uint2 ho;
        ho.x = pack_h(__float2half_rn(v.x), __float2half_rn(v.y));
        ho.y = pack_h(__float2half_rn(v.z), __float2half_rn(v.w));
        *reinterpret_cast<uint2*>(g_dw_hi + i) = ho;
    }
}
// x -> straight hi (B role) AND transposed hi (A role); all stores >= 8B.
__global__ __launch_bounds__(256) void conv_x(const float* __restrict__ x,
                                              const float* __restrict__ gamma) {
    if (gamma[0] != 0.0f) return;
    __shared__ float t[64][65];
    int n0 = blockIdx.x * 64, d0 = blockIdx.y * 64, b = blockIdx.z;
    int tid = threadIdx.x;
    int c4 = tid & 15, r = tid >> 4;
    const float* xb = x + (size_t)b * NF * DIM;
    #pragma unroll
    for (int i = 0; i < 4; i++) {
        int nl = r + 16 * i;
        int n = n0 + nl;
        float4 v = *reinterpret_cast<const float4*>(&xb[(size_t)n * DIM + d0 + c4 * 4]);
        t[nl][c4*4+0] = v.x; t[nl][c4*4+1] = v.y; t[nl][c4*4+2] = v.z; t[nl][c4*4+3] = v.w;
        uint2 ho;
        ho.x = pack_h(__float2half_rn(v.x), __float2half_rn(v.y));
        ho.y = pack_h(__float2half_rn(v.z), __float2half_rn(v.w));
        size_t o = (size_t)b * NF * DIM + (size_t)n * DIM + d0 + c4 * 4;
        *reinterpret_cast<uint2*>(&g_x_hi[o]) = ho;
    }
    __syncthreads();
    #pragma unroll
    for (int i = 0; i < 4; i++) {
        int dl = r + 16 * i;
        int d = d0 + dl;
        float v0 = t[c4*4+0][dl], v1 = t[c4*4+1][dl], v2 = t[c4*4+2][dl], v3 = t[c4*4+3][dl];
        uint2 ho;
        ho.x = pack_h(__float2half_rn(v0), __float2half_rn(v1));
        ho.y = pack_h(__float2half_rn(v2), __float2half_rn(v3));
        size_t o = (size_t)b * DIM * NF + (size_t)d * NF + n0 + c4 * 4;
        *reinterpret_cast<uint2*>(&g_xT_hi[o]) = ho;
    }
}

// ================= gamma != 0 fallback (SIMT f32x2 path) =====================
__global__ __launch_bounds__(256) void qkv_kernel(const float* __restrict__ x,
                                                  const float* __restrict__ w,
                                                  const float* __restrict__ bias,
                                                  const float* __restrict__ gamma) {
    if (gamma[0] == 0.0f) return;
    __shared__ float xs[DIM];
    for (int row = blockIdx.x; row < BATCH*NF; row += gridDim.x) {
        xs[threadIdx.x] = x[(long)row*DIM + threadIdx.x];
        __syncthreads();
        for (int e = threadIdx.x; e < 3*DIM; e += 256) {
            float acc = bias[e];
            const float* wr = w + (long)e*DIM;
            #pragma unroll 4
            for (int d = 0; d < DIM; d++) acc += xs[d]*wr[d];
            float* dst = (e < DIM) ? g_q : (e < 2*DIM ? g_k : g_v);
            dst[(long)row*DIM + (e & (DIM-1))] = acc;
        }
        __syncthreads();
    }
}
__global__ __launch_bounds__(256) void attn_kernel(const float* __restrict__ gamma) {
    if (gamma[0] == 0.0f) return;
    __shared__ float qs[DIM];
    __shared__ float es[NF];
    __shared__ float red[256];
    int t = threadIdx.x;
    for (int bn = blockIdx.x; bn < BATCH*NF; bn += gridDim.x) {
        int bb = bn / NF;
        qs[t] = g_q[(long)bn*DIM + t];
        __syncthreads();
        const float* kbase = g_k + (long)bb*NF*DIM;
        for (int m = t; m < NF; m += 256) {
            float acc = 0.0f;
            const float* kr = kbase + (long)m*DIM;
            #pragma unroll 4
            for (int d = 0; d < DIM; d++) acc += qs[d]*kr[d];
            es[m] = acc;
        }
        __syncthreads();
        float mx = -INFINITY;
        for (int m = t; m < NF; m += 256) mx = fmaxf(mx, es[m]);
        red[t] = mx; __syncthreads();
        for (int s = 128; s > 0; s >>= 1) { if (t < s) red[t] = fmaxf(red[t], red[t+s]); __syncthreads(); }
        mx = red[0]; __syncthreads();
        float sm = 0.0f;
        for (int m = t; m < NF; m += 256) { float e = expf(es[m]-mx); es[m] = e; sm += e; }
        red[t] = sm; __syncthreads();
        for (int s = 128; s > 0; s >>= 1) { if (t < s) red[t] += red[t+s]; __syncthreads(); }
        float inv = 1.0f / red[0];
        __syncthreads();
        const float* vbase = g_v + (long)bb*NF*DIM;
        float acc = 0.0f;
        for (int m = 0; m < NF; m++) acc += es[m]*vbase[(long)m*DIM + t];
        g_ao[(long)bn*DIM + t] = acc * inv;
        __syncthreads();
    }
}
__global__ __launch_bounds__(256) void xc_kernel(const float* __restrict__ x,
                                                 const float* __restrict__ gamma) {
    float g = gamma[0];
    if (g == 0.0f) return;
    for (long i = (long)blockIdx.x*256 + threadIdx.x; i < (long)BATCH*2*NF*DIM; i += (long)gridDim.x*256) {
        long b = i / (2L*NF*DIM);
        long r2 = i % (2L*NF*DIM);
        long c = r2 / DIM, l = r2 % DIM;
        float val;
        if (c < NF) { long s = (b*NF + c)*DIM + l; val = g*g_ao[s] + x[s]; }
        else        { long s = (b*NF + (c-NF))*DIM + l; val = x[s]; }
        g_xc[i] = val;
    }
}

#define TM 128
#define TN 128
#define TK 16
__device__ __forceinline__ unsigned long long splat2(float a) {
    unsigned long long r; unsigned int u = __float_as_uint(a);
    asm("mov.b64 %0, {%1, %1};" : "=l"(r) : "r"(u));
    return r;
}
__device__ __forceinline__ void fma2(unsigned long long& d, unsigned long long a, unsigned long long b) {
    asm("fma.rn.f32x2 %0, %1, %2, %0;" : "+l"(d) : "l"(a), "l"(b));
}
__device__ __forceinline__ float2 unpack2(unsigned long long v) {
    unsigned int lo, hi;
    asm("mov.b64 {%0, %1}, %2;" : "=r"(lo), "=r"(hi) : "l"(v));
    return make_float2(__uint_as_float(lo), __uint_as_float(hi));
}
template<int EPI>
__device__ __forceinline__ void sgemm_body(const float* __restrict__ A,
                                           const float* __restrict__ Bp,
                                           const float* __restrict__ bias,
                                           float* __restrict__ C, int N, int K,
                                           int bx, int by) {
    __shared__ float As[TK][TM];
    __shared__ float Bs[TK][TN];
    int tid = threadIdx.x;
    int tx = tid & 15, ty = tid >> 4;
    int rowBase = by * TM;
    int colBase = bx * TN;
    int ar = tid >> 1, ac = (tid & 1) << 3;
    int bk = tid >> 4, bn = (tid & 15) << 3;
    unsigned long long acc2[8][4];
    #pragma unroll
    for (int i = 0; i < 8; i++)
        #pragma unroll
        for (int j = 0; j < 4; j++) acc2[i][j] = 0ull;
    for (int k0 = 0; k0 < K; k0 += TK) {
        float4 a0 = *reinterpret_cast<const float4*>(&A[(long)(rowBase + ar)*K + k0 + ac]);
        float4 a1 = *reinterpret_cast<const float4*>(&A[(long)(rowBase + ar)*K + k0 + ac + 4]);
        float4 b0 = *reinterpret_cast<const float4*>(&Bp[(long)(k0 + bk)*N + colBase + bn]);
        float4 b1 = *reinterpret_cast<const float4*>(&Bp[(long)(k0 + bk)*N + colBase + bn + 4]);
        As[ac+0][ar] = a0.x; As[ac+1][ar] = a0.y; As[ac+2][ar] = a0.z; As[ac+3][ar] = a0.w;
        As[ac+4][ar] = a1.x; As[ac+5][ar] = a1.y; As[ac+6][ar] = a1.z; As[ac+7][ar] = a1.w;
        *reinterpret_cast<float4*>(&Bs[bk][bn])     = b0;
        *reinterpret_cast<float4*>(&Bs[bk][bn + 4]) = b1;
        __syncthreads();
        #pragma unroll
        for (int kk = 0; kk < TK; kk++) {
            float4 af0 = *reinterpret_cast<const float4*>(&As[kk][ty << 3]);
            float4 af1 = *reinterpret_cast<const float4*>(&As[kk][(ty << 3) + 4]);
            const unsigned long long* bpp = reinterpret_cast<const unsigned long long*>(&Bs[kk][tx << 3]);
            unsigned long long bb0 = bpp[0], bb1 = bpp[1], bb2 = bpp[2], bb3 = bpp[3];
            float av[8] = {af0.x, af0.y, af0.z, af0.w, af1.x, af1.y, af1.z, af1.w};
            #pragma unroll
            for (int i = 0; i < 8; i++) {
                unsigned long long aa = splat2(av[i]);
                fma2(acc2[i][0], aa, bb0); fma2(acc2[i][1], aa, bb1);
                fma2(acc2[i][2], aa, bb2); fma2(acc2[i][3], aa, bb3);
            }
        }
        __syncthreads();
    }
    #pragma unroll
    for (int i = 0; i < 8; i++) {
        int row = rowBase + (ty << 3) + i;
        float bv = (EPI == 1 || EPI == 3) ? bias[row] : 0.0f;
        float v[8];
        #pragma unroll
        for (int j = 0; j < 4; j++) {
            float2 p = unpack2(acc2[i][j]);
            v[2*j] = p.x + bv; v[2*j+1] = p.y + bv;
        }
        #pragma unroll
        for (int j = 0; j < 8; j++) {
            if (EPI == 1) v[j] = 1.0f/(1.0f + expf(-v[j]));
            if (EPI == 2 || EPI == 3) v[j] = (v[j] >= 0.f) ? v[j] : NEG*v[j];
        }
        *reinterpret_cast<float4*>(&C[(long)row*N + colBase + (tx << 3)])     = make_float4(v[0],v[1],v[2],v[3]);
        *reinterpret_cast<float4*>(&C[(long)row*N + colBase + (tx << 3) + 4]) = make_float4(v[4],v[5],v[6],v[7]);
    }
}
// grid-stride tile loop: gx*gy tiles per batch, BATCH batches
__global__ __launch_bounds__(256) void simtA(const float* __restrict__ gamma,
                                             const float* __restrict__ fc_w,
                                             const float* __restrict__ fc_b) {
    if (gamma[0] == 0.0f) return;
    const int gx = DIM/TN, gy = DIM/TM;
    int nT = gx * gy * BATCH;
    for (int t = blockIdx.x; t < nT; t += gridDim.x) {
        int bz = t / (gx*gy); int r = t % (gx*gy);
        sgemm_body<1>(fc_w, g_xc + (long)bz*2*NF*DIM, fc_b,
                      g_D + (long)bz*DIM*DIM, DIM, 2*NF, r % gx, r / gx);
    }
}
template<int EPI>
__global__ __launch_bounds__(256) void simtG(const float* __restrict__ gamma,
                                             const float* __restrict__ Ag,
                                             const float* __restrict__ Bg,
                                             const float* __restrict__ bias,
                                             float* __restrict__ Cg,
                                             int N, int K, long sA, long sB, long sC,
                                             int gx, int gy) {
    if (gamma[0] == 0.0f) return;
    int nT = gx * gy * BATCH;
    for (int t = blockIdx.x; t < nT; t += gridDim.x) {
        int bz = t / (gx*gy); int r = t % (gx*gy);
        sgemm_body<EPI>(Ag + (long)bz*sA, Bg + (long)bz*sB, bias,
                        Cg + (long)bz*sC, N, K, r % gx, r / gx);
    }
}

// ================= launch ====================================================
extern "C" void kernel_launch(void* const* d_in, const int* in_sizes, int n_in,
                              void* d_out, int out_size) {
    const float *x = 0, *qkv_w = 0, *qkv_b = 0, *gamma = 0, *fc_w = 0, *fc_b = 0, *dw_w = 0, *dw_b = 0;
    for (int i = 0; i < n_in; i++) {
        switch (in_sizes[i]) {
            case BATCH*NF*DIM: x     = (const float*)d_in[i]; break;
            case 3*DIM*DIM:    qkv_w = (const float*)d_in[i]; break;
            case 3*DIM:        qkv_b = (const float*)d_in[i]; break;
            case 1:            gamma = (const float*)d_in[i]; break;
            case DIM*2*NF:     fc_w  = (const float*)d_in[i]; break;
            case DIM:          fc_b  = (const float*)d_in[i]; break;
            case NF*NF:        dw_w  = (const float*)d_in[i]; break;
            case NF:           dw_b  = (const float*)d_in[i]; break;
        }
    }
    float* out = (float*)d_out;

    const int DSMEM = NSTAGE * STAGE_F;   // 110592
    cudaFuncSetAttribute(tgA, cudaFuncAttributeMaxDynamicSharedMemorySize, DSMEM);
    cudaFuncSetAttribute(tgB, cudaFuncAttributeMaxDynamicSharedMemorySize, DSMEM);
    cudaFuncSetAttribute(tgC, cudaFuncAttributeMaxDynamicSharedMemorySize, DSMEM);

    float *pD, *pY;
    cudaGetSymbolAddress((void**)&pD, g_D);
    cudaGetSymbolAddress((void**)&pY, g_Y);

    // ---- gamma == 0 tensor path (device-guarded) ----
    conv_weights<<<2048, 256>>>(fc_w, dw_w, gamma);                                // 1
    conv_x      <<<dim3(NF/64, DIM/64, BATCH), 256>>>(x, gamma);                   // 2
    tgA<<<dim3(2, 2, BATCH), 256, DSMEM>>>(gamma, fc_b);                           // 3
    tgB<<<dim3(8, 2, BATCH), 256, DSMEM>>>(gamma);                                 // 4
    tgC<<<dim3(2, 8, BATCH), 256, DSMEM>>>(gamma, dw_b, out);                      // 5
    // ---- gamma != 0 fallback (device-guarded; grid-stride, small grids) ----
    qkv_kernel <<<296, 256>>>(x, qkv_w, qkv_b, gamma);                             // 6 (ncu -s 5)
    attn_kernel<<<296, 256>>>(gamma);
    xc_kernel  <<<296, 256>>>(x, gamma);
    simtA<<<296, 256>>>(gamma, fc_w, fc_b);
    simtG<2><<<296, 256>>>(gamma, x, pD, nullptr, pY,
        DIM, DIM, (long)NF*DIM, (long)DIM*DIM, (long)NF*DIM, DIM/TN, NF/TM);
    simtG<3><<<296, 256>>>(gamma, dw_w, pY, dw_b, out,
        DIM, NF, 0L, (long)NF*DIM, (long)NF*DIM, DIM/TN, NF/TM);
}

// round 17
// speedup vs baseline: 1.0641x; 1.0641x over previous
#include <cuda_runtime.h>
#include <cuda_fp16.h>
#include <math.h>
#include <stdint.h>

#define BATCH 64
#define NF    1024
#define DIM   256
#define NEG   0.2f

// ================= device scratch (no allocs allowed) ========================
// gamma != 0 fallback path (fp32)
__device__ __align__(16) float g_q [BATCH*NF*DIM];
__device__ __align__(16) float g_k [BATCH*NF*DIM];
__device__ __align__(16) float g_v [BATCH*NF*DIM];
__device__ __align__(16) float g_ao[BATCH*NF*DIM];
__device__ __align__(16) float g_xc[BATCH*2*NF*DIM];
__device__ __align__(16) float g_D [BATCH*DIM*DIM];
__device__ __align__(16) float g_Y [BATCH*NF*DIM];
// gamma == 0 tensor path (fp16, single-term everywhere)
__device__ __align__(16) __half g_ws_hi[DIM*NF];
__device__ __align__(16) __half g_x_hi [BATCH*NF*DIM];
__device__ __align__(16) __half g_xT_hi[BATCH*DIM*NF];
__device__ __align__(16) __half g_dw_hi[NF*NF];
__device__ __align__(16) __half g_DT_hi[BATCH*DIM*DIM];
__device__ __align__(16) __half g_YT_hi[BATCH*DIM*NF];

// ================= PTX helpers (family-safe: sm_80-era only) =================
__device__ __forceinline__ uint32_t s2u(const void* p) {
    uint32_t a;
    asm("{ .reg .u64 t; cvta.to.shared.u64 t, %1; cvt.u32.u64 %0, t; }" : "=r"(a) : "l"(p));
    return a;
}
__device__ __forceinline__ void cp16(uint32_t dst, const void* src) {
    asm volatile("cp.async.cg.shared.global [%0], [%1], 16;" :: "r"(dst), "l"(src));
}
#define CP_COMMIT() asm volatile("cp.async.commit_group;" ::: "memory")
#define CP_WAIT2()  asm volatile("cp.async.wait_group 2;"  ::: "memory")
#define CP_WAIT1()  asm volatile("cp.async.wait_group 1;"  ::: "memory")
#define CP_WAIT0()  asm volatile("cp.async.wait_group 0;"  ::: "memory")

__device__ __forceinline__ void ldm_x4(uint32_t& r0, uint32_t& r1, uint32_t& r2, uint32_t& r3,
                                       uint32_t addr) {
    asm volatile("ldmatrix.sync.aligned.m8n8.x4.shared.b16 {%0,%1,%2,%3}, [%4];"
                 : "=r"(r0), "=r"(r1), "=r"(r2), "=r"(r3) : "r"(addr));
}
__device__ __forceinline__ void mma_f16(float* c, const uint32_t* a, const uint32_t* b) {
    asm volatile("mma.sync.aligned.m16n8k16.row.col.f32.f16.f16.f32 "
                 "{%0,%1,%2,%3}, {%4,%5,%6,%7}, {%8,%9}, {%0,%1,%2,%3};"
                 : "+f"(c[0]), "+f"(c[1]), "+f"(c[2]), "+f"(c[3])
                 : "r"(a[0]), "r"(a[1]), "r"(a[2]), "r"(a[3]), "r"(b[0]), "r"(b[1]));
}
__device__ __forceinline__ uint32_t pack_h(__half a, __half b) {
    return (uint32_t)__half_as_ushort(a) | ((uint32_t)__half_as_ushort(b) << 16);
}

// ================= fp16 single-term HMMA GEMM ================================
// C[M,N] = epi( A@B^T ), all K-major operands, fp32 accumulate.
// CTA 128x128, 256 threads, warp grid 4x2, warp tile 32x64, K-chunk 32
// (proven best — BK=64 starves the pipeline on short K).
// 4-stage cp.async pipeline, prefetch distance 3, in-loop wait_group 2:
// each fill gets ~2 chunk-periods of slack. ONE __syncthreads per chunk,
// loads for kk+3 issued BEFORE compute of kk.
// smem pitch 40 halfs (80B), conflict-free ldmatrix.
// EPI 1: sigmoid(acc + bias[col]) -> fp16 row-major out
// EPI 2: leaky(acc)               -> fp16 row-major out
// EPI 3: leaky(acc + bias[row])   -> fp32 row-major out
#define BK     32
#define PITCH  40
#define TILE_B 10240          // 128 rows x 40 halfs x 2B
#define STAGE_F (2*TILE_B)    // A | B  = 20480
#define NSTAGE 4              // 81920 B dyn smem; 2 CTAs = 160KB <= 228KB

template<int EPI>
__device__ void tgemm_body(const __half* __restrict__ Ahi,
                           const __half* __restrict__ Bhi,
                           int K, const float* __restrict__ bias,
                           __half* __restrict__ outH,
                           float* __restrict__ outF, int ldOut) {
    extern __shared__ char smc[];
    uint32_t sbase = s2u(smc);
    int tid = threadIdx.x, lane = tid & 31, wid = tid >> 5;   // 8 warps
    int mBase = blockIdx.y * 128, nBase = blockIdx.x * 128;
    int wRow = (wid >> 1) * 32, wCol = (wid & 1) * 64;

    int total = K / BK;
    int lrow = tid >> 1, lpart = tid & 1;

    auto load_stage = [&](int s, int kk) {
        int k0 = kk * BK;
        uint32_t st = sbase + (uint32_t)s * STAGE_F;
        #pragma unroll
        for (int t = 0; t < 2; t++) {
            const __half* S = t ? Bhi : Ahi;
            int rb = t ? nBase : mBase;
            const __half* rowp = S + (size_t)(rb + lrow) * K + k0 + lpart * 16;
            uint32_t dbase = st + (uint32_t)t * TILE_B + (uint32_t)(lrow * PITCH + lpart * 16) * 2;
            cp16(dbase,      rowp);
            cp16(dbase + 16, rowp + 8);
        }
        CP_COMMIT();
    };

    load_stage(0, 0);
    if (total > 1) load_stage(1, 1);
    if (total > 2) load_stage(2, 2);

    float acc[2][8][4];
    #pragma unroll
    for (int i = 0; i < 2; i++)
        #pragma unroll
        for (int j = 0; j < 8; j++)
            #pragma unroll
            for (int q = 0; q < 4; q++) acc[i][j][q] = 0.0f;

    int rs = 0, ws = 3;
    for (int kk = 0; kk < total; kk++) {
        if (kk + 2 < total)      { CP_WAIT2(); }
        else if (kk + 1 < total) { CP_WAIT1(); }
        else                     { CP_WAIT0(); }
        __syncthreads();
        // stage ws: last readers were iteration kk-1, already past the sync
        if (kk + 3 < total) load_stage(ws, kk + 3);

        uint32_t st = sbase + (uint32_t)rs * STAGE_F;
        uint32_t aT = st, bT = st + TILE_B;
        #pragma unroll
        for (int kf = 0; kf < 2; kf++) {
            uint32_t ah[2][4], bh[8][2];
            #pragma unroll
            for (int i = 0; i < 2; i++) {
                int r = wRow + i * 16 + (lane & 15);
                int c = kf * 16 + ((lane & 16) ? 8 : 0);
                ldm_x4(ah[i][0], ah[i][1], ah[i][2], ah[i][3],
                       aT + (uint32_t)(r * PITCH + c) * 2);
            }
            #pragma unroll
            for (int nf2 = 0; nf2 < 4; nf2++) {
                int n = wCol + nf2 * 16 + (lane & 7) + ((lane & 16) ? 8 : 0);
                int c = kf * 16 + ((lane & 8) ? 8 : 0);
                uint32_t r0, r1, r2, r3;
                ldm_x4(r0, r1, r2, r3, bT + (uint32_t)(n * PITCH + c) * 2);
                bh[nf2*2][0] = r0; bh[nf2*2][1] = r1;
                bh[nf2*2+1][0] = r2; bh[nf2*2+1][1] = r3;
            }
            #pragma unroll
            for (int i = 0; i < 2; i++)
                #pragma unroll
                for (int j = 0; j < 8; j++)
                    mma_f16(acc[i][j], ah[i], bh[j]);
        }
        rs = (rs == NSTAGE-1) ? 0 : rs + 1;
        ws = (ws == NSTAGE-1) ? 0 : ws + 1;
    }

    // ---- epilogue ----
    int r0 = mBase + wRow + (lane >> 2);
    int c0 = nBase + wCol + (lane & 3) * 2;
    #pragma unroll
    for (int i = 0; i < 2; i++) {
        #pragma unroll
        for (int h = 0; h < 2; h++) {
            int row = r0 + i * 16 + h * 8;
            float rbv = (EPI == 3) ? bias[row] : 0.0f;
            #pragma unroll
            for (int j = 0; j < 8; j++) {
                float v0 = acc[i][j][h*2+0];
                float v1 = acc[i][j][h*2+1];
                int col = c0 + j * 8;
                if (EPI == 1) {
                    v0 += bias[col]; v1 += bias[col + 1];
                    v0 = 1.0f / (1.0f + expf(-v0));
                    v1 = 1.0f / (1.0f + expf(-v1));
                } else if (EPI == 2) {
                    v0 = (v0 >= 0.f) ? v0 : NEG * v0;
                    v1 = (v1 >= 0.f) ? v1 : NEG * v1;
                } else {
                    v0 += rbv; v1 += rbv;
                    v0 = (v0 >= 0.f) ? v0 : NEG * v0;
                    v1 = (v1 >= 0.f) ? v1 : NEG * v1;
                }
                size_t off = (size_t)row * ldOut + col;
                if (EPI == 3) {
                    *reinterpret_cast<float2*>(outF + off) = make_float2(v0, v1);
                } else {
                    *reinterpret_cast<uint32_t*>(outH + off) =
                        pack_h(__float2half_rn(v0), __float2half_rn(v1));
                }
            }
        }
    }
}

// DT[l,o] = sigmoid( xT_b[l,:] . Wsum[o,:] + fc_b[o] )   M=256,N=256,K=1024
__global__ __launch_bounds__(256, 2)
void tgA(const float* __restrict__ gamma, const float* __restrict__ fc_b) {
    if (gamma[0] != 0.0f) return;
    size_t b = blockIdx.z;
    tgemm_body<1>(g_xT_hi + b * DIM * NF, g_ws_hi, NF, fc_b,
                  g_DT_hi + b * DIM * DIM, nullptr, DIM);
}
// YT[l,n] = leaky( DT_b[l,:] . x_b[n,:] )                 M=256,N=1024,K=256
__global__ __launch_bounds__(256, 2)
void tgB(const float* __restrict__ gamma) {
    if (gamma[0] != 0.0f) return;
    size_t b = blockIdx.z;
    tgemm_body<2>(g_DT_hi + b * DIM * DIM, g_x_hi + b * NF * DIM, DIM, nullptr,
                  g_YT_hi + b * DIM * NF, nullptr, NF);
}
// out[o,l] = leaky( dw[o,:] . YT_b[l,:] + dw_b[o] )       M=1024,N=256,K=1024
__global__ __launch_bounds__(256, 2)
void tgC(const float* __restrict__ gamma, const float* __restrict__ dw_b,
         float* __restrict__ out) {
    if (gamma[0] != 0.0f) return;
    size_t b = blockIdx.z;
    tgemm_body<3>(g_dw_hi, g_YT_hi + b * DIM * NF, NF, dw_b,
                  nullptr, out + b * NF * DIM, DIM);
}

// ================= conversion kernels (gamma == 0) ===========================
// weights: blocks [0,1024) -> wsum fold+convert; [1024,2048) -> dw convert
__global__ void conv_weights(const float* __restrict__ fc_w,
                             const float* __restrict__ dw_w,
                             const float* __restrict__ gamma) {
    if (gamma[0] != 0.0f) return;
    int blk = blockIdx.x;
    if (blk < 1024) {
        int i = blk * 256 + threadIdx.x;              // < DIM*NF
        int o = i >> 10, c = i & 1023;
        float w = fc_w[(size_t)o * 2048 + c] + fc_w[(size_t)o * 2048 + 1024 + c];
        g_ws_hi[i] = __float2half_rn(w);
    } else {
        size_t i = ((size_t)(blk - 1024) * 256 + threadIdx.x) * 4;   // < NF*NF
        float4 v = *reinterpret_cast<const float4*>(dw_w + i);
        uint2 ho;
        ho.x = pack_h(__float2half_rn(v.x), __float2half_rn(v.y));
        ho.y = pack_h(__float2half_rn(v.z), __float2half_rn(v.w));
        *reinterpret_cast<uint2*>(g_dw_hi + i) = ho;
    }
}
// x -> straight hi (B role) AND transposed hi (A role); all stores >= 8B.
__global__ __launch_bounds__(256) void conv_x(const float* __restrict__ x,
                                              const float* __restrict__ gamma) {
    if (gamma[0] != 0.0f) return;
    __shared__ float t[64][65];
    int n0 = blockIdx.x * 64, d0 = blockIdx.y * 64, b = blockIdx.z;
    int tid = threadIdx.x;
    int c4 = tid & 15, r = tid >> 4;
    const float* xb = x + (size_t)b * NF * DIM;
    #pragma unroll
    for (int i = 0; i < 4; i++) {
        int nl = r + 16 * i;
        int n = n0 + nl;
        float4 v = *reinterpret_cast<const float4*>(&xb[(size_t)n * DIM + d0 + c4 * 4]);
        t[nl][c4*4+0] = v.x; t[nl][c4*4+1] = v.y; t[nl][c4*4+2] = v.z; t[nl][c4*4+3] = v.w;
        uint2 ho;
        ho.x = pack_h(__float2half_rn(v.x), __float2half_rn(v.y));
        ho.y = pack_h(__float2half_rn(v.z), __float2half_rn(v.w));
        size_t o = (size_t)b * NF * DIM + (size_t)n * DIM + d0 + c4 * 4;
        *reinterpret_cast<uint2*>(&g_x_hi[o]) = ho;
    }
    __syncthreads();
    #pragma unroll
    for (int i = 0; i < 4; i++) {
        int dl = r + 16 * i;
        int d = d0 + dl;
        float v0 = t[c4*4+0][dl], v1 = t[c4*4+1][dl], v2 = t[c4*4+2][dl], v3 = t[c4*4+3][dl];
        uint2 ho;
        ho.x = pack_h(__float2half_rn(v0), __float2half_rn(v1));
        ho.y = pack_h(__float2half_rn(v2), __float2half_rn(v3));
        size_t o = (size_t)b * DIM * NF + (size_t)d * NF + n0 + c4 * 4;
        *reinterpret_cast<uint2*>(&g_xT_hi[o]) = ho;
    }
}

// ================= gamma != 0 fallback (SIMT f32x2 path) =====================
__global__ __launch_bounds__(256) void qkv_kernel(const float* __restrict__ x,
                                                  const float* __restrict__ w,
                                                  const float* __restrict__ bias,
                                                  const float* __restrict__ gamma) {
    if (gamma[0] == 0.0f) return;
    __shared__ float xs[DIM];
    for (int row = blockIdx.x; row < BATCH*NF; row += gridDim.x) {
        xs[threadIdx.x] = x[(long)row*DIM + threadIdx.x];
        __syncthreads();
        for (int e = threadIdx.x; e < 3*DIM; e += 256) {
            float acc = bias[e];
            const float* wr = w + (long)e*DIM;
            #pragma unroll 4
            for (int d = 0; d < DIM; d++) acc += xs[d]*wr[d];
            float* dst = (e < DIM) ? g_q : (e < 2*DIM ? g_k : g_v);
            dst[(long)row*DIM + (e & (DIM-1))] = acc;
        }
        __syncthreads();
    }
}
__global__ __launch_bounds__(256) void attn_kernel(const float* __restrict__ gamma) {
    if (gamma[0] == 0.0f) return;
    __shared__ float qs[DIM];
    __shared__ float es[NF];
    __shared__ float red[256];
    int t = threadIdx.x;
    for (int bn = blockIdx.x; bn < BATCH*NF; bn += gridDim.x) {
        int bb = bn / NF;
        qs[t] = g_q[(long)bn*DIM + t];
        __syncthreads();
        const float* kbase = g_k + (long)bb*NF*DIM;
        for (int m = t; m < NF; m += 256) {
            float acc = 0.0f;
            const float* kr = kbase + (long)m*DIM;
            #pragma unroll 4
            for (int d = 0; d < DIM; d++) acc += qs[d]*kr[d];
            es[m] = acc;
        }
        __syncthreads();
        float mx = -INFINITY;
        for (int m = t; m < NF; m += 256) mx = fmaxf(mx, es[m]);
        red[t] = mx; __syncthreads();
        for (int s = 128; s > 0; s >>= 1) { if (t < s) red[t] = fmaxf(red[t], red[t+s]); __syncthreads(); }
        mx = red[0]; __syncthreads();
        float sm = 0.0f;
        for (int m = t; m < NF; m += 256) { float e = expf(es[m]-mx); es[m] = e; sm += e; }
        red[t] = sm; __syncthreads();
        for (int s = 128; s > 0; s >>= 1) { if (t < s) red[t] += red[t+s]; __syncthreads(); }
        float inv = 1.0f / red[0];
        __syncthreads();
        const float* vbase = g_v + (long)bb*NF*DIM;
        float acc = 0.0f;
        for (int m = 0; m < NF; m++) acc += es[m]*vbase[(long)m*DIM + t];
        g_ao[(long)bn*DIM + t] = acc * inv;
        __syncthreads();
    }
}
__global__ __launch_bounds__(256) void xc_kernel(const float* __restrict__ x,
                                                 const float* __restrict__ gamma) {
    float g = gamma[0];
    if (g == 0.0f) return;
    for (long i = (long)blockIdx.x*256 + threadIdx.x; i < (long)BATCH*2*NF*DIM; i += (long)gridDim.x*256) {
        long b = i / (2L*NF*DIM);
        long r2 = i % (2L*NF*DIM);
        long c = r2 / DIM, l = r2 % DIM;
        float val;
        if (c < NF) { long s = (b*NF + c)*DIM + l; val = g*g_ao[s] + x[s]; }
        else        { long s = (b*NF + (c-NF))*DIM + l; val = x[s]; }
        g_xc[i] = val;
    }
}

#define TM 128
#define TN 128
#define TK 16
__device__ __forceinline__ unsigned long long splat2(float a) {
    unsigned long long r; unsigned int u = __float_as_uint(a);
    asm("mov.b64 %0, {%1, %1};" : "=l"(r) : "r"(u));
    return r;
}
__device__ __forceinline__ void fma2(unsigned long long& d, unsigned long long a, unsigned long long b) {
    asm("fma.rn.f32x2 %0, %1, %2, %0;" : "+l"(d) : "l"(a), "l"(b));
}
__device__ __forceinline__ float2 unpack2(unsigned long long v) {
    unsigned int lo, hi;
    asm("mov.b64 {%0, %1}, %2;" : "=r"(lo), "=r"(hi) : "l"(v));
    return make_float2(__uint_as_float(lo), __uint_as_float(hi));
}
template<int EPI>
__device__ __forceinline__ void sgemm_body(const float* __restrict__ A,
                                           const float* __restrict__ Bp,
                                           const float* __restrict__ bias,
                                           float* __restrict__ C, int N, int K,
                                           int bx, int by) {
    __shared__ float As[TK][TM];
    __shared__ float Bs[TK][TN];
    int tid = threadIdx.x;
    int tx = tid & 15, ty = tid >> 4;
    int rowBase = by * TM;
    int colBase = bx * TN;
    int ar = tid >> 1, ac = (tid & 1) << 3;
    int bk = tid >> 4, bn = (tid & 15) << 3;
    unsigned long long acc2[8][4];
    #pragma unroll
    for (int i = 0; i < 8; i++)
        #pragma unroll
        for (int j = 0; j < 4; j++) acc2[i][j] = 0ull;
    for (int k0 = 0; k0 < K; k0 += TK) {
        float4 a0 = *reinterpret_cast<const float4*>(&A[(long)(rowBase + ar)*K + k0 + ac]);
        float4 a1 = *reinterpret_cast<const float4*>(&A[(long)(rowBase + ar)*K + k0 + ac + 4]);
        float4 b0 = *reinterpret_cast<const float4*>(&Bp[(long)(k0 + bk)*N + colBase + bn]);
        float4 b1 = *reinterpret_cast<const float4*>(&Bp[(long)(k0 + bk)*N + colBase + bn + 4]);
        As[ac+0][ar] = a0.x; As[ac+1][ar] = a0.y; As[ac+2][ar] = a0.z; As[ac+3][ar] = a0.w;
        As[ac+4][ar] = a1.x; As[ac+5][ar] = a1.y; As[ac+6][ar] = a1.z; As[ac+7][ar] = a1.w;
        *reinterpret_cast<float4*>(&Bs[bk][bn])     = b0;
        *reinterpret_cast<float4*>(&Bs[bk][bn + 4]) = b1;
        __syncthreads();
        #pragma unroll
        for (int kk = 0; kk < TK; kk++) {
            float4 af0 = *reinterpret_cast<const float4*>(&As[kk][ty << 3]);
            float4 af1 = *reinterpret_cast<const float4*>(&As[kk][(ty << 3) + 4]);
            const unsigned long long* bpp = reinterpret_cast<const unsigned long long*>(&Bs[kk][tx << 3]);
            unsigned long long bb0 = bpp[0], bb1 = bpp[1], bb2 = bpp[2], bb3 = bpp[3];
            float av[8] = {af0.x, af0.y, af0.z, af0.w, af1.x, af1.y, af1.z, af1.w};
            #pragma unroll
            for (int i = 0; i < 8; i++) {
                unsigned long long aa = splat2(av[i]);
                fma2(acc2[i][0], aa, bb0); fma2(acc2[i][1], aa, bb1);
                fma2(acc2[i][2], aa, bb2); fma2(acc2[i][3], aa, bb3);
            }
        }
        __syncthreads();
    }
    #pragma unroll
    for (int i = 0; i < 8; i++) {
        int row = rowBase + (ty << 3) + i;
        float bv = (EPI == 1 || EPI == 3) ? bias[row] : 0.0f;
        float v[8];
        #pragma unroll
        for (int j = 0; j < 4; j++) {
            float2 p = unpack2(acc2[i][j]);
            v[2*j] = p.x + bv; v[2*j+1] = p.y + bv;
        }
        #pragma unroll
        for (int j = 0; j < 8; j++) {
            if (EPI == 1) v[j] = 1.0f/(1.0f + expf(-v[j]));
            if (EPI == 2 || EPI == 3) v[j] = (v[j] >= 0.f) ? v[j] : NEG*v[j];
        }
        *reinterpret_cast<float4*>(&C[(long)row*N + colBase + (tx << 3)])     = make_float4(v[0],v[1],v[2],v[3]);
        *reinterpret_cast<float4*>(&C[(long)row*N + colBase + (tx << 3) + 4]) = make_float4(v[4],v[5],v[6],v[7]);
    }
}
// grid-stride tile loop: gx*gy tiles per batch, BATCH batches
__global__ __launch_bounds__(256) void simtA(const float* __restrict__ gamma,
                                             const float* __restrict__ fc_w,
                                             const float* __restrict__ fc_b) {
    if (gamma[0] == 0.0f) return;
    const int gx = DIM/TN, gy = DIM/TM;
    int nT = gx * gy * BATCH;
    for (int t = blockIdx.x; t < nT; t += gridDim.x) {
        int bz = t / (gx*gy); int r = t % (gx*gy);
        sgemm_body<1>(fc_w, g_xc + (long)bz*2*NF*DIM, fc_b,
                      g_D + (long)bz*DIM*DIM, DIM, 2*NF, r % gx, r / gx);
    }
}
template<int EPI>
__global__ __launch_bounds__(256) void simtG(const float* __restrict__ gamma,
                                             const float* __restrict__ Ag,
                                             const float* __restrict__ Bg,
                                             const float* __restrict__ bias,
                                             float* __restrict__ Cg,
                                             int N, int K, long sA, long sB, long sC,
                                             int gx, int gy) {
    if (gamma[0] == 0.0f) return;
    int nT = gx * gy * BATCH;
    for (int t = blockIdx.x; t < nT; t += gridDim.x) {
        int bz = t / (gx*gy); int r = t % (gx*gy);
        sgemm_body<EPI>(Ag + (long)bz*sA, Bg + (long)bz*sB, bias,
                        Cg + (long)bz*sC, N, K, r % gx, r / gx);
    }
}

// ================= launch ====================================================
extern "C" void kernel_launch(void* const* d_in, const int* in_sizes, int n_in,
                              void* d_out, int out_size) {
    const float *x = 0, *qkv_w = 0, *qkv_b = 0, *gamma = 0, *fc_w = 0, *fc_b = 0, *dw_w = 0, *dw_b = 0;
    for (int i = 0; i < n_in; i++) {
        switch (in_sizes[i]) {
            case BATCH*NF*DIM: x     = (const float*)d_in[i]; break;
            case 3*DIM*DIM:    qkv_w = (const float*)d_in[i]; break;
            case 3*DIM:        qkv_b = (const float*)d_in[i]; break;
            case 1:            gamma = (const float*)d_in[i]; break;
            case DIM*2*NF:     fc_w  = (const float*)d_in[i]; break;
            case DIM:          fc_b  = (const float*)d_in[i]; break;
            case NF*NF:        dw_w  = (const float*)d_in[i]; break;
            case NF:           dw_b  = (const float*)d_in[i]; break;
        }
    }
    float* out = (float*)d_out;

    const int DSMEM = NSTAGE * STAGE_F;   // 81920
    cudaFuncSetAttribute(tgA, cudaFuncAttributeMaxDynamicSharedMemorySize, DSMEM);
    cudaFuncSetAttribute(tgB, cudaFuncAttributeMaxDynamicSharedMemorySize, DSMEM);
    cudaFuncSetAttribute(tgC, cudaFuncAttributeMaxDynamicSharedMemorySize, DSMEM);

    float *pD, *pY;
    cudaGetSymbolAddress((void**)&pD, g_D);
    cudaGetSymbolAddress((void**)&pY, g_Y);

    // ---- gamma == 0 tensor path (device-guarded) ----
    conv_weights<<<2048, 256>>>(fc_w, dw_w, gamma);                                // 1
    conv_x      <<<dim3(NF/64, DIM/64, BATCH), 256>>>(x, gamma);                   // 2
    tgA<<<dim3(2, 2, BATCH), 256, DSMEM>>>(gamma, fc_b);                           // 3
    tgB<<<dim3(8, 2, BATCH), 256, DSMEM>>>(gamma);                                 // 4
    tgC<<<dim3(2, 8, BATCH), 256, DSMEM>>>(gamma, dw_b, out);                      // 5
    // ---- gamma != 0 fallback (device-guarded; grid-stride, small grids) ----
    qkv_kernel <<<296, 256>>>(x, qkv_w, qkv_b, gamma);
    attn_kernel<<<296, 256>>>(gamma);
    xc_kernel  <<<296, 256>>>(x, gamma);
    simtA<<<296, 256>>>(gamma, fc_w, fc_b);
    simtG<2><<<296, 256>>>(gamma, x, pD, nullptr, pY,
        DIM, DIM, (long)NF*DIM, (long)DIM*DIM, (long)NF*DIM, DIM/TN, NF/TM);
    simtG<3><<<296, 256>>>(gamma, dw_w, pY, dw_b, out,
        DIM, NF, 0L, (long)NF*DIM, (long)NF*DIM, DIM/TN, NF/TM);
}